// round 14
// baseline (speedup 1.0000x reference)
#include <cuda_runtime.h>
#include <math.h>

#define NMOL 16
#define NATOM 64
#define RADF 64
#define ANGF 320
#define FEAT 384
#define RCR 5.2f
#define RCA 3.5f
#define FULL 0xffffffffu
#define TPB 256

__constant__ int c_triu16[16] = {
    0,1,2,3,
    1,4,5,6,
    2,5,7,8,
    3,6,8,9
};
// 0.5*cos / 0.5*sin of SHF_Z[z] = pi/16*(1+2z)
__constant__ float c_hcz[8] = {
     0.490392640201615224f,  0.415734806151272618f,  0.277785116509801112f,
     0.097545161008064134f, -0.097545161008064134f, -0.277785116509801112f,
    -0.415734806151272618f, -0.490392640201615224f
};
__constant__ float c_hsz[8] = {
     0.097545161008064134f,  0.277785116509801112f,  0.415734806151272618f,
     0.490392640201615224f,  0.490392640201615224f,  0.415734806151272618f,
     0.277785116509801112f,  0.097545161008064134f
};

__device__ __forceinline__ float pow32(float u) {
    u = fmaxf(u, 0.0f);
    u = u * u; u = u * u; u = u * u; u = u * u; u = u * u;
    return u;
}

// closed-form unordered-pair decode (validated R10/R11/R13)
__device__ __forceinline__ void decode_pair(int p, int npairs, int m_a,
                                            int& jj, int& kk) {
    const int t_ = npairs - 1 - p;
    int K = (int)((__fsqrt_rn((float)(8 * t_ + 1)) - 1.0f) * 0.5f);
    K += ((K + 1) * (K + 2) / 2 <= t_) ? 1 : 0;
    K -= (K * (K + 1) / 2 > t_) ? 1 : 0;
    jj = m_a - 2 - K;
    kk = m_a - 1 - (t_ - K * (K + 1) / 2);
}

__global__ __launch_bounds__(TPB, 8)
void aev_kernel(const int* __restrict__ species,
                const float* __restrict__ coords,
                float* __restrict__ out,
                int aev_base, int write_species)
{
    const int atom = blockIdx.x;          // 0..1023
    const int n = atom >> 6;
    const int i = atom & 63;
    const int tid  = threadIdx.x;
    const int lane = tid & 31;
    const int w    = tid >> 5;

    __shared__ float4 sP[NATOM];          // dx,dy,dz,d               (angular)
    __shared__ float4 sQ[NATOM];          // rinv, sqrt2*fca, spec, - (angular)
    __shared__ float4 sR[NATOM];          // d, 0.25*fcr, spec, -     (radial)
    __shared__ float  s_ang[ANGF];        // angular accumulators
    __shared__ float  pR[16 * 68];        // radial partials (pitch 68)

    // zero angular accumulators (all warps, fully parallel)
    if (tid < ANGF) s_ang[tid] = 0.0f;
    if (tid < ANGF - TPB) s_ang[tid + TPB] = 0.0f;

    // ===== prologue: all warps, halves processed SEQUENTIALLY (low regs) =====
    const float* cb = coords + (size_t)n * NATOM * 3;
    const float xi = __ldg(cb + 3 * i);       // uniform broadcast loads
    const float yi = __ldg(cb + 3 * i + 1);
    const float zi = __ldg(cb + 3 * i + 2);
    const unsigned lt = (1u << lane) - 1u;

    int m_r = 0, m_a = 0;
    #pragma unroll
    for (int h = 0; h < 2; h++) {
        const int j = lane + h * 32;
        const float dx = cb[j * 3 + 0] - xi;
        const float dy = cb[j * 3 + 1] - yi;
        const float dz = cb[j * 3 + 2] - zi;
        const int   sp = species[n * NATOM + j];
        const float d2 = fmaxf(dx * dx + dy * dy + dz * dz, 1e-20f);
        const float rinv = rsqrtf(d2);
        const float d = d2 * rinv;

        const bool self = (j == i);
        const bool vR = !self && (d <= RCR);
        const bool vA = !self && (d <= RCA);
        const unsigned mR = __ballot_sync(FULL, vR);
        const unsigned mA = __ballot_sync(FULL, vA);

        // role-specialized list writes; MUFU cos only where needed
        if (w == 0) {
            if (vR) {
                const float hr = 0.25f * (0.5f * __cosf((float)M_PI / RCR * d) + 0.5f);
                sR[m_r + __popc(mR & lt)]
                    = make_float4(d, hr, __int_as_float(sp), 0.f);
            }
        } else if (w == 1) {
            if (vA) sP[m_a + __popc(mA & lt)] = make_float4(dx, dy, dz, d);
        } else if (w == 2) {
            if (vA) {
                const float fca = 0.5f * __cosf((float)M_PI / RCA * d) + 0.5f;
                sQ[m_a + __popc(mA & lt)]
                    = make_float4(rinv, 1.41421356237f * fca, __int_as_float(sp), 0.f);
            }
        }
        m_r += __popc(mR);
        m_a += __popc(mA);
    }
    if (write_species && tid == 0) out[atom] = (float)species[n * NATOM + i];
    __syncthreads();                      // lists + zeroed s_ang ready

    // ===== radial: register accum, no atomics (R11/R13-validated) =====
    {
        const int r = tid & 15;
        const int g = tid >> 4;           // 0..15
        const float shf = 0.9f + 0.26875f * (float)r;
        float a0 = 0.f, a1 = 0.f, a2 = 0.f, a3 = 0.f;
        for (int q = g; q < m_r; q += 16) {
            const float4 e = sR[q];
            const int s = __float_as_int(e.z);
            const float t = e.x - shf;
            const float v = __expf(-16.0f * t * t) * e.y;
            a0 += (s == 0) ? v : 0.f;
            a1 += (s == 1) ? v : 0.f;
            a2 += (s == 2) ? v : 0.f;
            a3 += (s == 3) ? v : 0.f;
        }
        pR[g * 68 +  0 + r] = a0;
        pR[g * 68 + 16 + r] = a1;
        pR[g * 68 + 32 + r] = a2;
        pR[g * 68 + 48 + r] = a3;
    }

    // ===== angular: warp-per-pair, lane = (a,z) feature =====
    {
        const float sha = 0.9f + 0.65f * (float)(lane >> 3);
        const float hcz = c_hcz[lane & 7], hsz = c_hsz[lane & 7];
        const int npairs = m_a * (m_a - 1) / 2;
        for (int p = w; p < npairs; p += 8) {
            int jj, kk;
            decode_pair(p, npairs, m_a, jj, kk);
            const float4 Pj = sP[jj], Qj = sQ[jj];
            const float4 Pk = sP[kk], Qk = sQ[kk];
            const int pidx = c_triu16[__float_as_int(Qj.z) * 4 + __float_as_int(Qk.z)];

            float c = 0.95f * (Pj.x*Pk.x + Pj.y*Pk.y + Pj.z*Pk.z) * Qj.x * Qk.x;
            c = fminf(0.95f, fmaxf(-0.95f, c));
            const float s = sqrtf(1.0f - c * c);
            const float t2 = 0.5f * (Pj.w + Pk.w) - sha;
            const float f2 = __expf(-8.0f * t2 * t2);
            const float f1 = pow32(fmaf(c, hcz, fmaf(s, hsz, 0.5f)));
            atomicAdd(&s_ang[pidx * 32 + lane], Qj.y * Qk.y * f2 * f1);
        }
    }
    __syncthreads();

    // ===== epilogue: reduce radial partials + store =====
    float* ob = out + aev_base + (size_t)atom * FEAT;
    if (tid < RADF) {
        float sum = 0.f;
        #pragma unroll
        for (int g = 0; g < 16; g++) sum += pR[g * 68 + tid];
        ob[tid] = sum;
    }
    for (int f = tid; f < ANGF; f += TPB) ob[RADF + f] = s_ang[f];
}

extern "C" void kernel_launch(void* const* d_in, const int* in_sizes, int n_in,
                              void* d_out, int out_size)
{
    const int*   species = (const int*)d_in[0];
    const float* coords  = (const float*)d_in[1];
    float* out = (float*)d_out;

    const int total_atoms = NMOL * NATOM;       // 1024
    int aev_base = 0, write_species = 0;
    if (out_size >= total_atoms * FEAT + total_atoms) {
        aev_base = total_atoms;
        write_species = 1;
    }

    aev_kernel<<<total_atoms, TPB>>>(species, coords, out, aev_base, write_species);
}